// round 8
// baseline (speedup 1.0000x reference)
#include <cuda_runtime.h>
#include <cstdint>

// CTC loss forward — log2-domain forward recursion (tf.keras ctc_batch_cost
// semantics). One warp per batch element; states are log2(alpha), so each
// state carries its own exponent (no shared-base flush hazard — the failure
// mode of the linear-domain variants).
//
// Cost trick: 2^d is computed on the FMA pipe (exponent-split + deg-4 Taylor
// on [-0.5,0.5]); each logaddexp keeps exactly ONE MUFU (__log2f). 8 MUFU
// warp-ops/step vs 17 for the naive __expf/__logf version.
//
// State layout (S = 129), lane l in [0,32):
//   A0 = log2 alpha[2l]      (blank)     A1 = log2 alpha[2l+1]  (label lab[l])
//   A2 = log2 alpha[64+2l]   (blank)     A3 = log2 alpha[65+2l] (label lab[32+l])
//   A4 = log2 alpha[128]     (blank; lane 0 meaningful)
//
// Rotate shuffle: shfl(A1,(l-1)&31) -> lanes>=1 get alpha[2l-1], lane 0 gets
// alpha[63]; shfl(A3,(l-1)&31) -> lanes>=1 get alpha[63+2l], lane 0 alpha[127].

#define WARP_FULL 0xffffffffu
#define RCHUNK 8
#define NEGL  (-1e30f)
#define EPSV  (1e-7f)

// 2^d for d in [-24, 0] (caller clamps). Exponent-split + deg-4 Taylor.
__device__ __forceinline__ float p2_poly(float d) {
    float dm = d + 12582912.0f;            // 1.5*2^23 magic: dm = 12582912 + rint(d)
    float nf = dm - 12582912.0f;           // rint(d), exact
    float f  = d - nf;                     // [-0.5, 0.5]
    float p  = 0.0096181f;                 // ln2^4/24
    p = fmaf(p, f, 0.0555041f);            // ln2^3/6
    p = fmaf(p, f, 0.2402265f);            // ln2^2/2
    p = fmaf(p, f, 0.6931472f);            // ln2
    p = fmaf(p, f, 1.0f);
    int ni = __float_as_int(dm) - 0x4B400000;  // rint(d) as int (|d|<2^22)
    return __int_as_float(__float_as_int(p) + (ni << 23));
}

__device__ __forceinline__ float lae2_2(float a, float b) {           // log2-domain logaddexp
    float m = fmaxf(a, b);
    float d = fmaxf(fminf(a, b) - m, -24.0f);
    return m + __log2f(1.0f + p2_poly(d));
}

__device__ __forceinline__ float lae3_2(float a, float b, float c) {  // fused 3-way
    float m  = fmaxf(fmaxf(a, b), c);
    float ua = p2_poly(fmaxf(a - m, -24.0f));   // one of these is exactly 2^0 = 1
    float ub = p2_poly(fmaxf(b - m, -24.0f));
    float uc = p2_poly(fmaxf(c - m, -24.0f));
    return m + __log2f(ua + ub + uc);
}

__global__ __launch_bounds__(32, 1)
void ctc_fwd_log2_kernel(const int* __restrict__ y_true,
                         const float* __restrict__ y_pred,
                         const int* __restrict__ input_len,
                         const int* __restrict__ label_len,
                         float* __restrict__ out,
                         int T, int C, int Lmax)
{
    const int b = blockIdx.x;
    const int l = threadIdx.x;

    const float* P  = y_pred + (size_t)b * T * C;
    const int*  lab = y_true + (size_t)b * Lmax;

    int L = label_len[b];
    if (L > Lmax) L = Lmax;
    int Tlen = input_len[b];
    int tEnd = Tlen < 1 ? 1 : (Tlen > T ? T : Tlen);

    const int blank = C - 1;
    const float LN2 = 0.6931471805599453f;

    // per-lane label classes and skip flags
    const int c1  = lab[l];                 // state 2l+1
    const int c3  = lab[32 + l];            // state 65+2l
    const int c3m = lab[31 + l];
    const int c1m = (l >= 1) ? lab[l - 1] : -1;
    const bool skip1 = (l >= 1) && (c1 != c1m);
    const bool skip3 = (c3 != c3m);

    // ---- t = 0 init (log2 domain) ----
    float A0 = (l == 0)          ? __log2f(__ldg(P + blank) + EPSV) : NEGL;
    float A1 = (l == 0 && L > 0) ? __log2f(__ldg(P + c1)    + EPSV) : NEGL;
    float A2 = NEGL, A3 = NEGL, A4 = NEGL;

    // ---- prefetch raw probs for t = 1..RCHUNK ----
    float pb[RCHUNK], p1[RCHUNK], p3[RCHUNK];
    #pragma unroll
    for (int j = 0; j < RCHUNK; j++) {
        int t = 1 + j;
        const float* row = P + (size_t)(t < T ? t : T - 1) * C;
        pb[j] = __ldg(row + blank);
        p1[j] = __ldg(row + c1);
        p3[j] = __ldg(row + c3);
    }

    const int rsrc = (l + 31) & 31;         // rotate-by-1 source lane

    for (int tb = 1; tb < tEnd; tb += RCHUNK) {
        // issue next chunk's loads
        float nb[RCHUNK], n1b[RCHUNK], n3b[RCHUNK];
        #pragma unroll
        for (int j = 0; j < RCHUNK; j++) {
            int t = tb + RCHUNK + j;
            const float* row = P + (size_t)(t < T ? t : T - 1) * C;
            nb[j]  = __ldg(row + blank);
            n1b[j] = __ldg(row + c1);
            n3b[j] = __ldg(row + c3);
        }

        // precompute emissions (log2) for this chunk — off the serial chain
        float eb[RCHUNK], e1[RCHUNK], e3[RCHUNK];
        #pragma unroll
        for (int j = 0; j < RCHUNK; j++) {
            eb[j] = __log2f(pb[j] + EPSV);
            e1[j] = __log2f(p1[j] + EPSV);
            e3[j] = __log2f(p3[j] + EPSV);
        }

        #pragma unroll
        for (int j = 0; j < RCHUNK; j++) {
            int t = tb + j;

            float u1 = __shfl_sync(WARP_FULL, A1, rsrc); // l>=1: a[2l-1]; l0: a[63]
            float u3 = __shfl_sync(WARP_FULL, A3, rsrc); // l>=1: a[63+2l]; l0: a[127]

            float u1z = (l == 0) ? NEGL : u1;            // pred of s=2l
            float q   = (l == 0) ? u1   : u3;            // a[63+2l]
            float s1  = skip1 ? u1 : NEGL;
            float s3  = skip3 ? q  : NEGL;

            float n0v = lae2_2(A0, u1z)    + eb[j];      // s=2l
            float n1v = lae3_2(A1, A0, s1) + e1[j];      // s=2l+1
            float n2v = lae2_2(A2, q)      + eb[j];      // s=64+2l
            float n3v = lae3_2(A3, A2, s3) + e3[j];      // s=65+2l
            float n4v = lae2_2(A4, u3)     + eb[j];      // s=128 (lane 0)

            if (t < tEnd) { A0 = n0v; A1 = n1v; A2 = n2v; A3 = n3v; A4 = n4v; }
        }

        #pragma unroll
        for (int j = 0; j < RCHUNK; j++) { pb[j] = nb[j]; p1[j] = n1b[j]; p3[j] = n3b[j]; }
    }

    // ---- final readout: ll = ln2 * logaddexp2(a[2L], a[2L-1]) ----
    __shared__ float sA[129];
    sA[2 * l]      = A0;
    sA[2 * l + 1]  = A1;
    sA[64 + 2 * l] = A2;
    sA[65 + 2 * l] = A3;
    if (l == 0) sA[128] = A4;
    __syncwarp();

    if (l == 0) {
        float a_last = sA[2 * L];
        float a_prev = (L > 0) ? sA[2 * L - 1] : NEGL;
        float ll2 = lae2_2(a_last, a_prev);
        out[b] = -(ll2 * LN2);
    }
}

extern "C" void kernel_launch(void* const* d_in, const int* in_sizes, int n_in,
                              void* d_out, int out_size)
{
    const int*   y_true    = (const int*)  d_in[0];
    const float* y_pred    = (const float*)d_in[1];
    const int*   input_len = (const int*)  d_in[2];
    const int*   label_len = (const int*)  d_in[3];
    float* out = (float*)d_out;

    int B = out_size;                    // out is [B,1]
    int Lmax = in_sizes[0] / B;          // 64
    int C = 256;
    int T = in_sizes[1] / (B * C);       // 1024

    ctc_fwd_log2_kernel<<<B, 32>>>(y_true, y_pred, input_len, label_len, out, T, C, Lmax);
}